// round 16
// baseline (speedup 1.0000x reference)
#include <cuda_runtime.h>
#include <mma.h>
#include <cstdint>
#include <cstddef>
using namespace nvcuda;

#define TS    512
#define BATCH 128
#define D     512
#define H     512
#define NG3   1536
#define MT    (TS*BATCH)
#define NGC   128
#define BH_   ((size_t)BATCH*H)
#define TBH_  ((size_t)TS*BATCH*H)
#define LDW   516
#define LDO   80

// rec smem float offsets — steady state (aliases the init-time 64x516 B panel)
#define SM_A    0
#define SM_O    (32*LDW)                 // 16512
#define SM_F    (SM_O + 4*32*LDO)       // 26752 (unused slot, kept for alignment)
#define SM_GX   (SM_F + 32)              // 26784
#define SM_FX   (SM_GX + 1536)          // 28320
#define SM_B    (SM_FX + 64)             // 28384
#define SM_MLP  (SM_B + 48)              // 28432
#define SM_STEADY (SM_MLP + 20)          // 28452
#define SM_WTMP_F (64*LDW)               // 33024 floats init panel
#define REC_SMEM (SM_WTMP_F*4)           // 132096 B

// gemm_x smem: 3 stages x (256 rows x 36 floats)
#define GXS        3
#define GX_STAGE_F (256*36)
#define GX_SMEM    (GXS*GX_STAGE_F*4)

#define PREPX_BLOCKS (MT*D/1024)         // 32768

__device__ float    g_Gx[(size_t)MT*NG3];
__device__ float    g_Fx[(size_t)MT*2];
__device__ float    g_Xr[(size_t)MT*D];
__device__ float    g_Wx[(size_t)NG3*D];
__device__ float    g_Whh[(size_t)NG3*H];
__device__ float    g_bias[NG3];
__device__ unsigned g_flagw[(size_t)TS*NGC];

__device__ __forceinline__ float t32(float x){ return wmma::__float_to_tf32(x); }
__device__ __forceinline__ float sigm(float x){ return __fdividef(1.f, 1.f + __expf(-x)); }
__device__ __forceinline__ void cpa8(uint32_t dst, const void* src){
    asm volatile("cp.async.ca.shared.global [%0], [%1], 8;\n" :: "r"(dst), "l"(src));
}
__device__ __forceinline__ void cpa4(uint32_t dst, const void* src){
    asm volatile("cp.async.ca.shared.global [%0], [%1], 4;\n" :: "r"(dst), "l"(src));
}
__device__ __forceinline__ void cpa16(uint32_t dst, const void* src){
    asm volatile("cp.async.ca.shared.global [%0], [%1], 16;\n" :: "r"(dst), "l"(src));
}

// ---------- prep (merged): tf32-round X | pack weights | zero flags ----------
__global__ void prep_kernel(const float* __restrict__ X,
                            const float* __restrict__ Wi, const float* __restrict__ Wu,
                            const float* __restrict__ Wo, const float* __restrict__ bi,
                            const float* __restrict__ bu, const float* __restrict__ bo) {
    int bx = blockIdx.x;
    if (bx < PREPX_BLOCKS) {
        size_t i = ((size_t)bx*256 + threadIdx.x)*4;
        float4 v = *(const float4*)(X + i);
        float4 o; o.x=t32(v.x); o.y=t32(v.y); o.z=t32(v.z); o.w=t32(v.w);
        *(float4*)(g_Xr + i) = o;
        return;
    }
    int n = bx - PREPX_BLOCKS;
    if (n < NG3) {
        int g = n >> 9, j = n & 511;
        const float* W = (g==0) ? Wi : (g==1 ? Wu : Wo);
        const float* s = W + (size_t)j*(D+H);
        for (int k = threadIdx.x; k < D; k += blockDim.x) {
            g_Wx [(size_t)n*D + k] = t32(s[k]);
            g_Whh[(size_t)n*H + k] = t32(s[D+k]);
        }
        if (threadIdx.x == 0) g_bias[n] = (g==0 ? bi : (g==1 ? bu : bo))[j];
    } else {
        int base = (n - NG3) * 8192;
        for (int k = threadIdx.x; k < 8192; k += blockDim.x) g_flagw[base + k] = 0u;
    }
}

// ---------- x-part of forget logits (fp32 exact) ----------
__global__ void fx_kernel(const float* __restrict__ X, const float* __restrict__ Wf,
                          const float* __restrict__ bf) {
    int m = blockIdx.x*8 + (threadIdx.x>>5);
    int lane = threadIdx.x & 31;
    const float* x = X + (size_t)m*D;
    float s0 = 0.f, s1 = 0.f;
    #pragma unroll 4
    for (int k = lane; k < D; k += 32) {
        float xv = x[k];
        s0 += xv * __ldg(&Wf[k]);
        s1 += xv * __ldg(&Wf[1024+k]);
    }
    #pragma unroll
    for (int o = 16; o; o >>= 1) {
        s0 += __shfl_xor_sync(~0u, s0, o);
        s1 += __shfl_xor_sync(~0u, s1, o);
    }
    if (lane == 0) {
        g_Fx[(size_t)m*2+0] = s0 + __ldg(&bf[0]);
        g_Fx[(size_t)m*2+1] = s1 + __ldg(&bf[1]);
    }
}

// ---------- big parallel GEMM: Gx = Xr @ Wx.T (tf32 WMMA, cp.async pipeline) ----------
__global__ void __launch_bounds__(256) gemm_x() {
    extern __shared__ float sb[];
    uint32_t sbase = (uint32_t)__cvta_generic_to_shared(sb);
    int tid = threadIdx.x, wid = tid>>5;
    int n0 = blockIdx.x*128, m0 = blockIdx.y*128;
    int wm = wid>>1, wn = wid&1;
    int lr = tid>>3, lc = (tid&7)*4;

    wmma::fragment<wmma::accumulator,16,16,8,float> acc[2][4];
    #pragma unroll
    for (int i=0;i<2;i++)
        #pragma unroll
        for (int j=0;j<4;j++) wmma::fill_fragment(acc[i][j], 0.f);

    auto load_chunk = [&](int s, int kc) {
        const float* As = g_Xr + (size_t)m0*D + kc*32;
        const float* Bsrc = g_Wx + (size_t)n0*D + kc*32;
        uint32_t ds = sbase + (uint32_t)s*GX_STAGE_F*4;
        #pragma unroll
        for (int u = 0; u < 4; u++) {
            int rr = lr + u*32;
            cpa16(ds + (uint32_t)(rr*36+lc)*4,       As   + (size_t)rr*D + lc);
            cpa16(ds + (uint32_t)((128+rr)*36+lc)*4, Bsrc + (size_t)rr*D + lc);
        }
        asm volatile("cp.async.commit_group;\n");
    };

    load_chunk(0,0); load_chunk(1,1);
    for (int kc = 0; kc < 16; kc++) {
        asm volatile("cp.async.wait_group 1;\n");
        __syncthreads();
        if (kc+2 < 16) load_chunk((kc+2)%GXS, kc+2);
        else asm volatile("cp.async.commit_group;\n");
        float* As = sb + (kc%GXS)*GX_STAGE_F;
        float* Bs = As + 128*36;
        #pragma unroll
        for (int kk = 0; kk < 4; kk++) {
            wmma::fragment<wmma::matrix_a,16,16,8,wmma::precision::tf32,wmma::row_major> a0,a1;
            wmma::fragment<wmma::matrix_b,16,16,8,wmma::precision::tf32,wmma::col_major> b0,b1,b2,b3;
            wmma::load_matrix_sync(a0, &As[(wm*32+ 0)*36 + kk*8], 36);
            wmma::load_matrix_sync(a1, &As[(wm*32+16)*36 + kk*8], 36);
            wmma::load_matrix_sync(b0, &Bs[(wn*64+ 0)*36 + kk*8], 36);
            wmma::load_matrix_sync(b1, &Bs[(wn*64+16)*36 + kk*8], 36);
            wmma::load_matrix_sync(b2, &Bs[(wn*64+32)*36 + kk*8], 36);
            wmma::load_matrix_sync(b3, &Bs[(wn*64+48)*36 + kk*8], 36);
            wmma::mma_sync(acc[0][0], a0, b0, acc[0][0]);
            wmma::mma_sync(acc[0][1], a0, b1, acc[0][1]);
            wmma::mma_sync(acc[0][2], a0, b2, acc[0][2]);
            wmma::mma_sync(acc[0][3], a0, b3, acc[0][3]);
            wmma::mma_sync(acc[1][0], a1, b0, acc[1][0]);
            wmma::mma_sync(acc[1][1], a1, b1, acc[1][1]);
            wmma::mma_sync(acc[1][2], a1, b2, acc[1][2]);
            wmma::mma_sync(acc[1][3], a1, b3, acc[1][3]);
        }
    }
    #pragma unroll
    for (int i=0;i<2;i++)
        #pragma unroll
        for (int j=0;j<4;j++)
            wmma::store_matrix_sync(g_Gx + (size_t)(m0+wm*32+i*16)*NG3 + n0+wn*64+j*16,
                                    acc[i][j], NG3, wmma::mem_row_major);
}

// ---------- persistent recurrent kernel: 128 CTAs x 512 threads ----------
// ALL 16 warps do GEMM: col-tile wc = wid&3 (gates i/u/o + [f0,f1,pad]), K-quarter kq = wid>>2.
// f-gate = 2 extra GEMM columns; epilogue computes the tiny MLP per-thread.
__global__ void __launch_bounds__(512,1) rec_kernel(
        float* __restrict__ out, const float* __restrict__ Wf,
        const float* __restrict__ Ws1, const float* __restrict__ bs1,
        const float* __restrict__ Ws2, const float* __restrict__ bs2,
        long long out_size) {
    extern __shared__ float sm[];
    float* sA   = sm + SM_A;
    float* sO   = sm + SM_O;
    float* sGX  = sm + SM_GX;
    float* sFX  = sm + SM_FX;
    float* sB   = sm + SM_B;
    float* sMLP = sm + SM_MLP;
    float* sWtmp = sm;                   // init-only alias (64 x LDW B panel)
    uint32_t sGXb = (uint32_t)__cvta_generic_to_shared(sGX);
    uint32_t sFXb = (uint32_t)__cvta_generic_to_shared(sFX);
    int tid = threadIdx.x, wid = tid>>5, lane = tid&31;
    bool tail = out_size >= (long long)(TBH_ + 2*BH_);

    int rb = blockIdx.x >> 5, jt = blockIdx.x & 31;
    int row0 = rb*32, j0 = jt*16;

    int wc = wid & 3, kq = wid >> 2;     // all 16 warps: GEMM roles

    // ---- init: stage 64x512 B panel, load persistent fragments, then reuse smem ----
    for (int idx = tid; idx < 64*512; idx += 512) {
        int row = idx >> 9, k = idx & 511;
        float v;
        if (row < 48)       v = g_Whh[(size_t)((row>>4)*512 + j0 + (row&15))*H + k];
        else if (row == 48) v = t32(Wf[512+k]);
        else if (row == 49) v = t32(Wf[1536+k]);
        else                v = 0.f;
        sWtmp[row*LDW + k] = v;
    }
    __syncthreads();
    wmma::fragment<wmma::matrix_b,16,16,8,wmma::precision::tf32,wmma::col_major> bfr[16];
    #pragma unroll
    for (int q = 0; q < 16; q++)
        wmma::load_matrix_sync(bfr[q], &sWtmp[(wc*16)*LDW + (kq*16+q)*8], LDW);
    __syncthreads();
    // small tables (overlap the now-dead B panel region)
    if (tid < 48) sB[tid] = g_bias[(tid>>4)*512 + j0 + (tid&15)];
    if (tid == 0) {
        #pragma unroll
        for (int i=0;i<8;i++) sMLP[i] = Ws1[i];
        #pragma unroll
        for (int i=0;i<4;i++) { sMLP[8+i] = bs1[i]; sMLP[12+i] = Ws2[i] - Ws2[4+i]; }
        sMLP[16] = bs2[0] - bs2[1];
    }

    // epilogue slot: 1 output per thread
    int rp = tid>>4, jp = tid&15;
    int bq = row0+rp, jj = j0+jp;
    float cst = 0.f;
    __syncthreads();

    for (int t = 0; t < TS; t++) {
        // A) async prefetch of x-part preactivations (no registers held)
        {
            const float* gsrc = g_Gx + ((size_t)t*BATCH + bq)*NG3 + jj;
            cpa4(sGXb + (uint32_t)tid*4,        gsrc);
            cpa4(sGXb + (uint32_t)(512+tid)*4,  gsrc + 512);
            cpa4(sGXb + (uint32_t)(1024+tid)*4, gsrc + 1024);
            if (wid == 15) {
                cpa8(sFXb + (uint32_t)lane*8, g_Fx + ((size_t)t*BATCH + row0 + lane)*2);
            }
            asm volatile("cp.async.commit_group;\n");
        }

        // B) wait for producers (one warp polls), then stage h[t-1]
        if (t > 0) {
            if (wid == 0) {
                volatile unsigned* fl = &g_flagw[(size_t)(t-1)*NGC + rb*32 + lane];
                while (*fl == 0u) {}
            }
            __syncthreads();
            const float* hb = out + (size_t)(t-1)*BH_;
            #pragma unroll
            for (int u = 0; u < 8; u++) {
                int f4 = tid + u*512;
                int r = f4 >> 7, c4 = f4 & 127;
                float4 v = *(const float4*)(hb + (size_t)(row0+r)*H + c4*4);
                float* d = &sA[r*LDW + c4*4];
                d[0]=t32(v.x); d[1]=t32(v.y); d[2]=t32(v.z); d[3]=t32(v.w);
            }
        }
        __syncthreads();

        // C) GEMM: every warp does its (wc, kq) tile — 16 mma iters
        {
            wmma::fragment<wmma::accumulator,16,16,8,float> acc0, acc1;
            wmma::fill_fragment(acc0, 0.f);
            wmma::fill_fragment(acc1, 0.f);
            if (t > 0) {
                #pragma unroll
                for (int q = 0; q < 16; q++) {
                    int kk = kq*16 + q;
                    wmma::fragment<wmma::matrix_a,16,16,8,wmma::precision::tf32,wmma::row_major> a0, a1;
                    wmma::load_matrix_sync(a0, &sA[kk*8], LDW);
                    wmma::load_matrix_sync(a1, &sA[16*LDW + kk*8], LDW);
                    wmma::mma_sync(acc0, a0, bfr[q], acc0);
                    wmma::mma_sync(acc1, a1, bfr[q], acc1);
                }
            }
            wmma::store_matrix_sync(&sO[(kq*32+ 0)*LDO + wc*16], acc0, LDO, wmma::mem_row_major);
            wmma::store_matrix_sync(&sO[(kq*32+16)*LDO + wc*16], acc1, LDO, wmma::mem_row_major);
        }
        __syncthreads();

        // D) epilogue: f-gate (per-thread, broadcast reads) + gates + LSTM update
        asm volatile("cp.async.wait_group 0;\n" ::: "memory");
        float fl0 = sFX[rp*2], fl1 = sFX[rp*2+1];
        #pragma unroll
        for (int q = 0; q < 4; q++) {
            fl0 += sO[(q*32+rp)*LDO + 48];
            fl1 += sO[(q*32+rp)*LDO + 49];
        }
        float m0 = tanhf(sMLP[0]*fl0 + sMLP[1]*fl1 + sMLP[8]);
        float m1 = tanhf(sMLP[2]*fl0 + sMLP[3]*fl1 + sMLP[9]);
        float m2 = tanhf(sMLP[4]*fl0 + sMLP[5]*fl1 + sMLP[10]);
        float m3 = tanhf(sMLP[6]*fl0 + sMLP[7]*fl1 + sMLP[11]);
        float fv = sigm(sMLP[12]*m0 + sMLP[13]*m1 + sMLP[14]*m2 + sMLP[15]*m3 + sMLP[16]);

        float gi = sGX[tid], gu = sGX[512+tid], go = sGX[1024+tid];
        float pi = sO[(  rp)*LDO + jp]      + sO[(32+rp)*LDO + jp]
                 + sO[(64+rp)*LDO + jp]     + sO[(96+rp)*LDO + jp]      + gi + sB[jp];
        float pu = sO[(  rp)*LDO + 16+jp]   + sO[(32+rp)*LDO + 16+jp]
                 + sO[(64+rp)*LDO + 16+jp]  + sO[(96+rp)*LDO + 16+jp]   + gu + sB[16+jp];
        float po = sO[(  rp)*LDO + 32+jp]   + sO[(32+rp)*LDO + 32+jp]
                 + sO[(64+rp)*LDO + 32+jp]  + sO[(96+rp)*LDO + 32+jp]   + go + sB[32+jp];
        cst = fv*cst + sigm(pi)*tanhf(pu);
        float hv = sigm(po)*tanhf(cst);
        out[(size_t)t*BH_ + (size_t)bq*H + jj] = hv;
        if (t == TS-1 && tail) {
            out[TBH_ + (size_t)bq*H + jj] = hv;
            out[TBH_ + BH_ + (size_t)bq*H + jj] = cst;
        }
        // parallel per-warp drain of global stores, then publish
        asm volatile("membar.gl;" ::: "memory");
        __syncthreads();
        if (tid == 0) *(volatile unsigned*)&g_flagw[(size_t)t*NGC + blockIdx.x] = 1u;
    }
}

extern "C" void kernel_launch(void* const* d_in, const int* in_sizes, int n_in,
                              void* d_out, int out_size) {
    const float* X   = (const float*)d_in[0];
    const float* Wf  = (const float*)d_in[1];
    const float* bf  = (const float*)d_in[2];
    const float* Wi  = (const float*)d_in[3];
    const float* bi  = (const float*)d_in[4];
    const float* Wu  = (const float*)d_in[5];
    const float* bu  = (const float*)d_in[6];
    const float* Wo  = (const float*)d_in[7];
    const float* bo  = (const float*)d_in[8];
    const float* Ws1 = (const float*)d_in[9];
    const float* bs1 = (const float*)d_in[10];
    const float* Ws2 = (const float*)d_in[11];
    const float* bs2 = (const float*)d_in[12];
    float* out = (float*)d_out;

    cudaFuncSetAttribute(rec_kernel, cudaFuncAttributeMaxDynamicSharedMemorySize, REC_SMEM);
    cudaFuncSetAttribute(gemm_x,     cudaFuncAttributeMaxDynamicSharedMemorySize, GX_SMEM);

    prep_kernel<<<PREPX_BLOCKS + NG3 + 8, 256>>>(X, Wi, Wu, Wo, bi, bu, bo);
    fx_kernel<<<MT/8, 256>>>(X, Wf, bf);
    dim3 g(NG3/128, MT/128);
    gemm_x<<<g, 256, GX_SMEM>>>();
    rec_kernel<<<NGC, 512, REC_SMEM>>>(out, Wf, Ws1, bs1, Ws2, bs2, (long long)out_size);
}

// round 17
// speedup vs baseline: 1.2079x; 1.2079x over previous
#include <cuda_runtime.h>
#include <mma.h>
#include <cstdint>
#include <cstddef>
using namespace nvcuda;

#define TS    512
#define BATCH 128
#define D     512
#define H     512
#define NG3   1536
#define MT    (TS*BATCH)
#define NGC   128
#define BH_   ((size_t)BATCH*H)
#define TBH_  ((size_t)TS*BATCH*H)
#define LDW   516
#define LDO   48

// rec smem float offsets
#define SM_W    0
#define SM_A    (48*LDW)                 // 24768
#define SM_O    (SM_A + 32*LDW)          // 41280
#define SM_F    (SM_O + 4*32*LDO)        // 47424
#define SM_WF   (SM_F + 32)              // 47456
#define SM_GX   (SM_WF + 1024)           // 48480
#define SM_FX   (SM_GX + 1536)           // 50016
#define SM_B    (SM_FX + 64)             // 50080
#define SM_MLP  (SM_B + 48)              // 50128
#define SM_TOT  (SM_MLP + 20)            // 50148
#define REC_SMEM (SM_TOT*4)              // 200592 B

// gemm_x smem: 3 stages x (256 rows x 36 floats)
#define GXS        3
#define GX_STAGE_F (256*36)
#define GX_SMEM    (GXS*GX_STAGE_F*4)

#define PREPX_BLOCKS (MT*D/1024)         // 32768

__device__ float    g_Gx[(size_t)MT*NG3];
__device__ float    g_Fx[(size_t)MT*2];
__device__ float    g_Xr[(size_t)MT*D];
__device__ float    g_Wx[(size_t)NG3*D];
__device__ float    g_Whh[(size_t)NG3*H];
__device__ float    g_bias[NG3];
__device__ unsigned g_flagw[(size_t)TS*NGC];

__device__ __forceinline__ float t32(float x){ return wmma::__float_to_tf32(x); }
__device__ __forceinline__ float sigm(float x){ return __fdividef(1.f, 1.f + __expf(-x)); }
__device__ __forceinline__ void cpa8(uint32_t dst, const void* src){
    asm volatile("cp.async.ca.shared.global [%0], [%1], 8;\n" :: "r"(dst), "l"(src));
}
__device__ __forceinline__ void cpa4(uint32_t dst, const void* src){
    asm volatile("cp.async.ca.shared.global [%0], [%1], 4;\n" :: "r"(dst), "l"(src));
}
__device__ __forceinline__ void cpa16(uint32_t dst, const void* src){
    asm volatile("cp.async.ca.shared.global [%0], [%1], 16;\n" :: "r"(dst), "l"(src));
}

// ---------- prep (merged): tf32-round X | pack weights | zero flags ----------
__global__ void prep_kernel(const float* __restrict__ X,
                            const float* __restrict__ Wi, const float* __restrict__ Wu,
                            const float* __restrict__ Wo, const float* __restrict__ bi,
                            const float* __restrict__ bu, const float* __restrict__ bo) {
    int bx = blockIdx.x;
    if (bx < PREPX_BLOCKS) {
        size_t i = ((size_t)bx*256 + threadIdx.x)*4;
        float4 v = *(const float4*)(X + i);
        float4 o; o.x=t32(v.x); o.y=t32(v.y); o.z=t32(v.z); o.w=t32(v.w);
        *(float4*)(g_Xr + i) = o;
        return;
    }
    int n = bx - PREPX_BLOCKS;
    if (n < NG3) {
        int g = n >> 9, j = n & 511;
        const float* W = (g==0) ? Wi : (g==1 ? Wu : Wo);
        const float* s = W + (size_t)j*(D+H);
        for (int k = threadIdx.x; k < D; k += blockDim.x) {
            g_Wx [(size_t)n*D + k] = t32(s[k]);
            g_Whh[(size_t)n*H + k] = t32(s[D+k]);
        }
        if (threadIdx.x == 0) g_bias[n] = (g==0 ? bi : (g==1 ? bu : bo))[j];
    } else {
        int base = (n - NG3) * 8192;
        for (int k = threadIdx.x; k < 8192; k += blockDim.x) g_flagw[base + k] = 0u;
    }
}

// ---------- x-part of forget logits (fp32 exact) ----------
__global__ void fx_kernel(const float* __restrict__ X, const float* __restrict__ Wf,
                          const float* __restrict__ bf) {
    int m = blockIdx.x*8 + (threadIdx.x>>5);
    int lane = threadIdx.x & 31;
    const float* x = X + (size_t)m*D;
    float s0 = 0.f, s1 = 0.f;
    #pragma unroll 4
    for (int k = lane; k < D; k += 32) {
        float xv = x[k];
        s0 += xv * __ldg(&Wf[k]);
        s1 += xv * __ldg(&Wf[1024+k]);
    }
    #pragma unroll
    for (int o = 16; o; o >>= 1) {
        s0 += __shfl_xor_sync(~0u, s0, o);
        s1 += __shfl_xor_sync(~0u, s1, o);
    }
    if (lane == 0) {
        g_Fx[(size_t)m*2+0] = s0 + __ldg(&bf[0]);
        g_Fx[(size_t)m*2+1] = s1 + __ldg(&bf[1]);
    }
}

// ---------- big parallel GEMM: Gx = Xr @ Wx.T (tf32 WMMA, cp.async pipeline) ----------
__global__ void __launch_bounds__(256) gemm_x() {
    extern __shared__ float sb[];
    uint32_t sbase = (uint32_t)__cvta_generic_to_shared(sb);
    int tid = threadIdx.x, wid = tid>>5;
    int n0 = blockIdx.x*128, m0 = blockIdx.y*128;
    int wm = wid>>1, wn = wid&1;
    int lr = tid>>3, lc = (tid&7)*4;

    wmma::fragment<wmma::accumulator,16,16,8,float> acc[2][4];
    #pragma unroll
    for (int i=0;i<2;i++)
        #pragma unroll
        for (int j=0;j<4;j++) wmma::fill_fragment(acc[i][j], 0.f);

    auto load_chunk = [&](int s, int kc) {
        const float* As = g_Xr + (size_t)m0*D + kc*32;
        const float* Bsrc = g_Wx + (size_t)n0*D + kc*32;
        uint32_t ds = sbase + (uint32_t)s*GX_STAGE_F*4;
        #pragma unroll
        for (int u = 0; u < 4; u++) {
            int rr = lr + u*32;
            cpa16(ds + (uint32_t)(rr*36+lc)*4,       As   + (size_t)rr*D + lc);
            cpa16(ds + (uint32_t)((128+rr)*36+lc)*4, Bsrc + (size_t)rr*D + lc);
        }
        asm volatile("cp.async.commit_group;\n");
    };

    load_chunk(0,0); load_chunk(1,1);
    for (int kc = 0; kc < 16; kc++) {
        asm volatile("cp.async.wait_group 1;\n");
        __syncthreads();
        if (kc+2 < 16) load_chunk((kc+2)%GXS, kc+2);
        else asm volatile("cp.async.commit_group;\n");
        float* As = sb + (kc%GXS)*GX_STAGE_F;
        float* Bs = As + 128*36;
        #pragma unroll
        for (int kk = 0; kk < 4; kk++) {
            wmma::fragment<wmma::matrix_a,16,16,8,wmma::precision::tf32,wmma::row_major> a0,a1;
            wmma::fragment<wmma::matrix_b,16,16,8,wmma::precision::tf32,wmma::col_major> b0,b1,b2,b3;
            wmma::load_matrix_sync(a0, &As[(wm*32+ 0)*36 + kk*8], 36);
            wmma::load_matrix_sync(a1, &As[(wm*32+16)*36 + kk*8], 36);
            wmma::load_matrix_sync(b0, &Bs[(wn*64+ 0)*36 + kk*8], 36);
            wmma::load_matrix_sync(b1, &Bs[(wn*64+16)*36 + kk*8], 36);
            wmma::load_matrix_sync(b2, &Bs[(wn*64+32)*36 + kk*8], 36);
            wmma::load_matrix_sync(b3, &Bs[(wn*64+48)*36 + kk*8], 36);
            wmma::mma_sync(acc[0][0], a0, b0, acc[0][0]);
            wmma::mma_sync(acc[0][1], a0, b1, acc[0][1]);
            wmma::mma_sync(acc[0][2], a0, b2, acc[0][2]);
            wmma::mma_sync(acc[0][3], a0, b3, acc[0][3]);
            wmma::mma_sync(acc[1][0], a1, b0, acc[1][0]);
            wmma::mma_sync(acc[1][1], a1, b1, acc[1][1]);
            wmma::mma_sync(acc[1][2], a1, b2, acc[1][2]);
            wmma::mma_sync(acc[1][3], a1, b3, acc[1][3]);
        }
    }
    #pragma unroll
    for (int i=0;i<2;i++)
        #pragma unroll
        for (int j=0;j<4;j++)
            wmma::store_matrix_sync(g_Gx + (size_t)(m0+wm*32+i*16)*NG3 + n0+wn*64+j*16,
                                    acc[i][j], NG3, wmma::mem_row_major);
}

// ---------- persistent recurrent kernel: 128 CTAs x 512 threads (R8-best structure) ----------
__global__ void __launch_bounds__(512,1) rec_kernel(
        float* __restrict__ out, const float* __restrict__ Wf,
        const float* __restrict__ Ws1, const float* __restrict__ bs1,
        const float* __restrict__ Ws2, const float* __restrict__ bs2,
        long long out_size) {
    extern __shared__ float sm[];
    float* sW   = sm + SM_W;
    float* sA   = sm + SM_A;
    float* sO   = sm + SM_O;
    float* sF   = sm + SM_F;
    float* sWf  = sm + SM_WF;
    float* sGX  = sm + SM_GX;
    float* sFX  = sm + SM_FX;
    float* sB   = sm + SM_B;
    float* sMLP = sm + SM_MLP;
    uint32_t sGXb = (uint32_t)__cvta_generic_to_shared(sGX);
    uint32_t sFXb = (uint32_t)__cvta_generic_to_shared(sFX);
    int tid = threadIdx.x, wid = tid>>5, lane = tid&31;
    bool tail = out_size >= (long long)(TBH_ + 2*BH_);

    int rb = blockIdx.x >> 5, jt = blockIdx.x & 31;
    int row0 = rb*32, j0 = jt*16;

    // one-time smem setup
    for (int idx = tid; idx < 48*512; idx += 512) {
        int row = idx >> 9, k = idx & 511;
        sW[row*LDW + k] = g_Whh[(size_t)((row>>4)*512 + j0 + (row&15))*H + k];
    }
    for (int k = tid; k < 512; k += 512) { sWf[k] = Wf[512+k]; sWf[512+k] = Wf[1536+k]; }
    if (tid < 48) sB[tid] = g_bias[(tid>>4)*512 + j0 + (tid&15)];
    if (tid == 0) {
        #pragma unroll
        for (int i=0;i<8;i++) sMLP[i] = Ws1[i];
        #pragma unroll
        for (int i=0;i<4;i++) { sMLP[8+i] = bs1[i]; sMLP[12+i] = Ws2[i] - Ws2[4+i]; }
        sMLP[16] = bs2[0] - bs2[1];
    }

    // epilogue slot: 1 output per thread
    int rp = tid>>4, jp = tid&15;
    int bq = row0+rp, jj = j0+jp;
    float cst = 0.f;

    int wc = wid >> 2, kq = wid & 3;     // GEMM roles (wid<12)
    int fw = wid - 12, rbase = fw*8;     // f roles (wid>=12)
    __syncthreads();

    // preload B fragments into registers (persist across all 512 steps)
    wmma::fragment<wmma::matrix_b,16,16,8,wmma::precision::tf32,wmma::col_major> bfr[16];
    if (wid < 12) {
        #pragma unroll
        for (int q = 0; q < 16; q++)
            wmma::load_matrix_sync(bfr[q], &sW[(wc*16)*LDW + (kq*16+q)*8], LDW);
    }
    __syncthreads();

    for (int t = 0; t < TS; t++) {
        // A) async prefetch of x-part preactivations (no registers held)
        {
            const float* gsrc = g_Gx + ((size_t)t*BATCH + bq)*NG3 + jj;
            cpa4(sGXb + (uint32_t)tid*4,        gsrc);
            cpa4(sGXb + (uint32_t)(512+tid)*4,  gsrc + 512);
            cpa4(sGXb + (uint32_t)(1024+tid)*4, gsrc + 1024);
            if (wid >= 12 && lane < 8) {
                int r = rbase + lane;
                cpa8(sFXb + (uint32_t)r*8, g_Fx + ((size_t)t*BATCH + row0 + r)*2);
            }
            asm volatile("cp.async.commit_group;\n");
        }

        // B) wait for producers (one warp polls), then stage h[t-1]
        if (t > 0) {
            if (wid == 0) {
                volatile unsigned* fl = &g_flagw[(size_t)(t-1)*NGC + rb*32 + lane];
                while (*fl == 0u) {}
            }
            __syncthreads();
            const float* hb = out + (size_t)(t-1)*BH_;
            #pragma unroll
            for (int u = 0; u < 8; u++) {
                int f4 = tid + u*512;
                int r = f4 >> 7, c4 = f4 & 127;
                float4 v = *(const float4*)(hb + (size_t)(row0+r)*H + c4*4);
                float* d = &sA[r*LDW + c4*4];
                d[0]=t32(v.x); d[1]=t32(v.y); d[2]=t32(v.z); d[3]=t32(v.w);
            }
        }
        __syncthreads();

        if (wid < 12) {
            // gate GEMM: cols [wc*16..+16), K-quarter kq — manual double-buffered A prefetch
            wmma::fragment<wmma::accumulator,16,16,8,float> acc0, acc1;
            wmma::fill_fragment(acc0, 0.f);
            wmma::fill_fragment(acc1, 0.f);
            if (t > 0) {
                wmma::fragment<wmma::matrix_a,16,16,8,wmma::precision::tf32,wmma::row_major> a0[2], a1[2];
                int kk0 = kq*16;
                wmma::load_matrix_sync(a0[0], &sA[kk0*8], LDW);
                wmma::load_matrix_sync(a1[0], &sA[16*LDW + kk0*8], LDW);
                #pragma unroll
                for (int q = 0; q < 16; q++) {
                    int cur = q & 1, nxt = cur ^ 1;
                    if (q < 15) {
                        int kk = kk0 + q + 1;
                        wmma::load_matrix_sync(a0[nxt], &sA[kk*8], LDW);
                        wmma::load_matrix_sync(a1[nxt], &sA[16*LDW + kk*8], LDW);
                    }
                    wmma::mma_sync(acc0, a0[cur], bfr[q], acc0);
                    wmma::mma_sync(acc1, a1[cur], bfr[q], acc1);
                }
            }
            wmma::store_matrix_sync(&sO[(kq*32+ 0)*LDO + wc*16], acc0, LDO, wmma::mem_row_major);
            wmma::store_matrix_sync(&sO[(kq*32+16)*LDO + wc*16], acc1, LDO, wmma::mem_row_major);
        } else {
            // forget gate from staged sA (tf32) — weights loaded per step (short liveness)
            float4 wa0 = *(const float4*)&sWf[      0*128 + lane*4];
            float4 wa1 = *(const float4*)&sWf[      1*128 + lane*4];
            float4 wa2 = *(const float4*)&sWf[      2*128 + lane*4];
            float4 wa3 = *(const float4*)&sWf[      3*128 + lane*4];
            float4 wb0 = *(const float4*)&sWf[512 + 0*128 + lane*4];
            float4 wb1 = *(const float4*)&sWf[512 + 1*128 + lane*4];
            float4 wb2 = *(const float4*)&sWf[512 + 2*128 + lane*4];
            float4 wb3 = *(const float4*)&sWf[512 + 3*128 + lane*4];
            float p0[8], p1[8];
            #pragma unroll
            for (int r=0;r<8;r++){ p0[r]=0.f; p1[r]=0.f; }
            if (t > 0) {
                #pragma unroll
                for (int r = 0; r < 8; r++) {
                    const float* ar = &sA[(rbase+r)*LDW];
                    float4 v0 = *(const float4*)&ar[0*128 + lane*4];
                    float4 v1 = *(const float4*)&ar[1*128 + lane*4];
                    float4 v2 = *(const float4*)&ar[2*128 + lane*4];
                    float4 v3 = *(const float4*)&ar[3*128 + lane*4];
                    p0[r] = v0.x*wa0.x+v0.y*wa0.y+v0.z*wa0.z+v0.w*wa0.w
                          + v1.x*wa1.x+v1.y*wa1.y+v1.z*wa1.z+v1.w*wa1.w
                          + v2.x*wa2.x+v2.y*wa2.y+v2.z*wa2.z+v2.w*wa2.w
                          + v3.x*wa3.x+v3.y*wa3.y+v3.z*wa3.z+v3.w*wa3.w;
                    p1[r] = v0.x*wb0.x+v0.y*wb0.y+v0.z*wb0.z+v0.w*wb0.w
                          + v1.x*wb1.x+v1.y*wb1.y+v1.z*wb1.z+v1.w*wb1.w
                          + v2.x*wb2.x+v2.y*wb2.y+v2.z*wb2.z+v2.w*wb2.w
                          + v3.x*wb3.x+v3.y*wb3.y+v3.z*wb3.z+v3.w*wb3.w;
                }
            }
            #pragma unroll
            for (int r = 0; r < 8; r++) {
                #pragma unroll
                for (int o = 16; o; o >>= 1) {
                    p0[r] += __shfl_xor_sync(~0u, p0[r], o);
                    p1[r] += __shfl_xor_sync(~0u, p1[r], o);
                }
            }
            asm volatile("cp.async.wait_group 0;\n" ::: "memory");
            if (lane < 8) {
                float a0=0.f, a1=0.f;
                #pragma unroll
                for (int r = 0; r < 8; r++) if (lane == r) { a0 = p0[r]; a1 = p1[r]; }
                int rr = rbase + lane;
                float fl0 = a0 + sFX[rr*2], fl1 = a1 + sFX[rr*2+1];
                float h0 = tanhf(sMLP[0]*fl0 + sMLP[1]*fl1 + sMLP[8]);
                float h1 = tanhf(sMLP[2]*fl0 + sMLP[3]*fl1 + sMLP[9]);
                float h2 = tanhf(sMLP[4]*fl0 + sMLP[5]*fl1 + sMLP[10]);
                float h3 = tanhf(sMLP[6]*fl0 + sMLP[7]*fl1 + sMLP[11]);
                float dl = sMLP[12]*h0 + sMLP[13]*h1 + sMLP[14]*h2 + sMLP[15]*h3 + sMLP[16];
                sF[rr] = sigm(dl);
            }
        }
        __syncthreads();

        // epilogue: sum 4 K-quarter partials + x-part (from smem) + bias; LSTM update
        asm volatile("cp.async.wait_group 0;\n" ::: "memory");
        float gi = sGX[tid], gu = sGX[512+tid], go = sGX[1024+tid];
        float fv = sF[rp];
        float pi = sO[(  rp)*LDO + jp]      + sO[(32+rp)*LDO + jp]
                 + sO[(64+rp)*LDO + jp]     + sO[(96+rp)*LDO + jp]      + gi + sB[jp];
        float pu = sO[(  rp)*LDO + 16+jp]   + sO[(32+rp)*LDO + 16+jp]
                 + sO[(64+rp)*LDO + 16+jp]  + sO[(96+rp)*LDO + 16+jp]   + gu + sB[16+jp];
        float po = sO[(  rp)*LDO + 32+jp]   + sO[(32+rp)*LDO + 32+jp]
                 + sO[(64+rp)*LDO + 32+jp]  + sO[(96+rp)*LDO + 32+jp]   + go + sB[32+jp];
        cst = fv*cst + sigm(pi)*tanhf(pu);
        float hv = sigm(po)*tanhf(cst);
        out[(size_t)t*BH_ + (size_t)bq*H + jj] = hv;
        if (t == TS-1 && tail) {
            out[TBH_ + (size_t)bq*H + jj] = hv;
            out[TBH_ + BH_ + (size_t)bq*H + jj] = cst;
        }
        __syncthreads();
        if (tid == 0) {
            __threadfence();
            *(volatile unsigned*)&g_flagw[(size_t)t*NGC + blockIdx.x] = 1u;
        }
    }
}

extern "C" void kernel_launch(void* const* d_in, const int* in_sizes, int n_in,
                              void* d_out, int out_size) {
    const float* X   = (const float*)d_in[0];
    const float* Wf  = (const float*)d_in[1];
    const float* bf  = (const float*)d_in[2];
    const float* Wi  = (const float*)d_in[3];
    const float* bi  = (const float*)d_in[4];
    const float* Wu  = (const float*)d_in[5];
    const float* bu  = (const float*)d_in[6];
    const float* Wo  = (const float*)d_in[7];
    const float* bo  = (const float*)d_in[8];
    const float* Ws1 = (const float*)d_in[9];
    const float* bs1 = (const float*)d_in[10];
    const float* Ws2 = (const float*)d_in[11];
    const float* bs2 = (const float*)d_in[12];
    float* out = (float*)d_out;

    cudaFuncSetAttribute(rec_kernel, cudaFuncAttributeMaxDynamicSharedMemorySize, REC_SMEM);
    cudaFuncSetAttribute(gemm_x,     cudaFuncAttributeMaxDynamicSharedMemorySize, GX_SMEM);

    prep_kernel<<<PREPX_BLOCKS + NG3 + 8, 256>>>(X, Wi, Wu, Wo, bi, bu, bo);
    fx_kernel<<<MT/8, 256>>>(X, Wf, bf);
    dim3 g(NG3/128, MT/128);
    gemm_x<<<g, 256, GX_SMEM>>>();
    rec_kernel<<<NGC, 512, REC_SMEM>>>(out, Wf, Ws1, bs1, Ws2, bs2, (long long)out_size);
}